// round 9
// baseline (speedup 1.0000x reference)
#include <cuda_runtime.h>

#define Bp 400
#define Np 8000
#define Dp 100
#define SCALERp 4

#define TILE 8                 // rows per warp-tile (ping-pong register buffer)
#define WARPS 4
#define THREADS 128
#define TILES_PER_WARP 50      // 400 rows per warp
#define ROWS_PER_BLOCK (WARPS * TILE * TILES_PER_WARP)   // 1600
#define BLOCKS_PER_B (Np / ROWS_PER_BLOCK)               // 5
#define TOTAL_BLOCKS (Bp * BLOCKS_PER_B)                 // 2000
#define RSTRIDE 28             // floats per buf row; 112B = 16B-aligned, conflict-free
#define BUFROWS 16             // rows 0-7: pa, rows 8-15: pb

// Deterministic per-(b,chunk) pooled partials: [B][BLOCKS_PER_B][D]
__device__ float g_partial[Bp * BLOCKS_PER_B * Dp];
__device__ int   g_cnt = 0;    // last-block election; self-resetting each launch

__device__ __forceinline__ float tanh_approx(float x) {
    float y;
    asm("tanh.approx.f32 %0, %1;" : "=f"(y) : "f"(x));
    return y;
}

__global__ __launch_bounds__(THREADS)
void fused_pass_kernel(const float* __restrict__ x,
                       const float* __restrict__ x_scaler,
                       const float* __restrict__ dim_weight,
                       const float* __restrict__ w,
                       float* __restrict__ out_small,
                       float* __restrict__ alpha_out,
                       float* __restrict__ beta_out)
{
    const int b    = blockIdx.x / BLOCKS_PER_B;
    const int c    = blockIdx.x % BLOCKS_PER_B;
    const int warp = threadIdx.x >> 5;
    const int lane = threadIdx.x & 31;

    __shared__ __align__(16) float s_red[WARPS][BUFROWS * RSTRIDE]; // 7.2 KB
    __shared__ float s_acc[WARPS][Dp];                              // 1.6 KB
    __shared__ bool  s_last;

    // Lane l (<25) owns dims [4l, 4l+4)
    float4 dw4 = make_float4(0.f, 0.f, 0.f, 0.f);
    float4 w14 = make_float4(0.f, 0.f, 0.f, 0.f);
    if (lane < 25) {
        dw4 = *reinterpret_cast<const float4*>(dim_weight + 4 * lane);
        w14.x = w[(4 * lane + 0) * 2 + 1];
        w14.y = w[(4 * lane + 1) * 2 + 1];
        w14.z = w[(4 * lane + 2) * 2 + 1];
        w14.w = w[(4 * lane + 3) * 2 + 1];
    }

    float4 acc = make_float4(0.f, 0.f, 0.f, 0.f);
    float* buf = s_red[warp];
    const long long rowbase = (long long)b * Np;

    // Reducing lanes: 0-7 sum pa rows 0-7; 16-23 sum pb rows 8-15.
    const bool redlane = (lane < 8) | ((lane >= 16) & (lane < 24));
    const int  redrow  = (lane < 8) ? lane : (lane - 8);   // buf row index

    // Ping-pong register tiles (8 rows each)
    float4 v[2][TILE];
    #pragma unroll
    for (int r = 0; r < TILE; r++) {
        v[0][r] = make_float4(0.f, 0.f, 0.f, 0.f);
        v[1][r] = make_float4(0.f, 0.f, 0.f, 0.f);
    }

    // Preload tile 0
    {
        const int n0 = c * ROWS_PER_BLOCK + warp * TILE;
        const float4* base4 =
            reinterpret_cast<const float4*>(x + (rowbase + n0) * Dp);
        if (lane < 25) {
            #pragma unroll
            for (int r = 0; r < TILE; r++) v[0][r] = base4[r * 25 + lane];
        }
    }

    #pragma unroll 2
    for (int t = 0; t < TILES_PER_WARP; t++) {
        const int cur = t & 1;
        const int n0  = c * ROWS_PER_BLOCK + (t * WARPS + warp) * TILE;

        // ---- 1. Prefetch next tile (loads stay in flight through the tile)
        if ((t + 1 < TILES_PER_WARP) & (lane < 25)) {
            const int n1 = c * ROWS_PER_BLOCK + ((t + 1) * WARPS + warp) * TILE;
            const float4* nb =
                reinterpret_cast<const float4*>(x + (rowbase + n1) * Dp);
            #pragma unroll
            for (int r = 0; r < TILE; r++) v[cur ^ 1][r] = nb[r * 25 + lane];
        }

        // ---- 2. Partial dots, written ROW-MAJOR into the transpose buffer
        if (lane < 25) {
            #pragma unroll
            for (int r = 0; r < TILE; r++) {
                const float4 q = v[cur][r];
                buf[r * RSTRIDE + lane] =
                    (q.x * dw4.x + q.y * dw4.y) + (q.z * dw4.z + q.w * dw4.w);
                buf[(r + TILE) * RSTRIDE + lane] =
                    (q.x * w14.x + q.y * w14.y) + (q.z * w14.z + q.w * w14.w);
            }
        }
        __syncwarp();

        // ---- 3. Vectorized tree reduce: 6 LDS.128 + 1 LDS.32, depth-5 adds
        float sum = 0.f;
        if (redlane) {
            const float4* row = reinterpret_cast<const float4*>(buf + redrow * RSTRIDE);
            const float4 a0 = row[0], a1 = row[1], a2 = row[2];
            const float4 a3 = row[3], a4 = row[4], a5 = row[5];
            const float tail = buf[redrow * RSTRIDE + 24];
            const float t0 = (a0.x + a0.y) + (a0.z + a0.w);
            const float t1 = (a1.x + a1.y) + (a1.z + a1.w);
            const float t2 = (a2.x + a2.y) + (a2.z + a2.w);
            const float t3 = (a3.x + a3.y) + (a3.z + a3.w);
            const float t4 = (a4.x + a4.y) + (a4.z + a4.w);
            const float t5 = (a5.x + a5.y) + (a5.z + a5.w);
            sum = ((t0 + t1) + (t2 + t3)) + ((t4 + t5) + tail);
        }
        const float a = tanh_approx(sum);   // valid in lanes 0..7 (rows 0..7)
        if (lane < 8)
            alpha_out[rowbase + n0 + lane] = a;
        else if (redlane)
            beta_out[rowbase + n0 + (lane - 16)] = sum;

        // ---- 4. Pooled accumulation from registers.
        // The shfl_sync convergence also guarantees every reducing lane has
        // consumed its LDS results before any lane reaches the next tile's
        // STS — no trailing __syncwarp needed.
        #pragma unroll
        for (int r = 0; r < TILE; r++) {
            const float ar = __shfl_sync(0xffffffffu, a, r);
            const float4 q = v[cur][r];
            acc.x += ar * q.x;
            acc.y += ar * q.y;
            acc.z += ar * q.z;
            acc.w += ar * q.w;
        }
    }

    // ---- Block-reduce the 4 warp accumulators (deterministic)
    if (lane < 25) {
        s_acc[warp][lane * 4 + 0] = acc.x;
        s_acc[warp][lane * 4 + 1] = acc.y;
        s_acc[warp][lane * 4 + 2] = acc.z;
        s_acc[warp][lane * 4 + 3] = acc.w;
    }
    __syncthreads();
    for (int d = threadIdx.x; d < Dp; d += THREADS) {
        float sum = 0.f;
        #pragma unroll
        for (int wp = 0; wp < WARPS; wp++) sum += s_acc[wp][d];
        g_partial[((long long)b * BLOCKS_PER_B + c) * Dp + d] = sum;
    }

    // ---- Last-arriving block performs the final [B,2] head (deterministic)
    __threadfence();
    if (threadIdx.x == 0) {
        int old = atomicAdd(&g_cnt, 1);
        s_last = (old == TOTAL_BLOCKS - 1);
    }
    __syncthreads();
    if (!s_last) return;
    if (threadIdx.x == 0) g_cnt = 0;      // reset for next graph replay

    for (int b2 = warp; b2 < Bp; b2 += WARPS) {
        float4 f4 = make_float4(0.f, 0.f, 0.f, 0.f);
        if (lane < 25) {
            #pragma unroll
            for (int cc = 0; cc < BLOCKS_PER_B; cc++) {
                const float4 g = *reinterpret_cast<const float4*>(
                    g_partial + ((long long)b2 * BLOCKS_PER_B + cc) * Dp + 4 * lane);
                f4.x += g.x; f4.y += g.y; f4.z += g.z; f4.w += g.w;
            }
        }
        float p0 = 0.f, p1 = 0.f;
        if (lane < 25) {
            p0 = f4.x * w[(4*lane+0)*2+0] + f4.y * w[(4*lane+1)*2+0]
               + f4.z * w[(4*lane+2)*2+0] + f4.w * w[(4*lane+3)*2+0];
            p1 = f4.x * w[(4*lane+0)*2+1] + f4.y * w[(4*lane+1)*2+1]
               + f4.z * w[(4*lane+2)*2+1] + f4.w * w[(4*lane+3)*2+1];
        }
        #pragma unroll
        for (int off = 16; off; off >>= 1) {
            p0 += __shfl_xor_sync(0xffffffffu, p0, off);
            p1 += __shfl_xor_sync(0xffffffffu, p1, off);
        }
        if (lane == 0) {
            #pragma unroll
            for (int s = 0; s < SCALERp; s++) {
                const float xs = x_scaler[b2 * SCALERp + s];
                p0 += xs * w[(Dp + s) * 2 + 0];
                p1 += xs * w[(Dp + s) * 2 + 1];
            }
            out_small[b2 * 2 + 0] = p0;
            out_small[b2 * 2 + 1] = p1;
        }
    }
}

extern "C" void kernel_launch(void* const* d_in, const int* in_sizes, int n_in,
                              void* d_out, int out_size)
{
    // metadata order == setup_inputs order: x, x_scaler, dim_weight, w
    const float* x          = (const float*)d_in[0];
    const float* x_scaler   = (const float*)d_in[1];
    const float* dim_weight = (const float*)d_in[2];
    const float* w          = (const float*)d_in[3];

    // Output flattening in reference-return order: out [B,2], alpha [B,1,N], beta [B,N]
    float* out_base  = (float*)d_out;
    float* out_small = out_base;                       // 800 floats
    float* alpha     = out_base + Bp * 2;              // 3,200,000 floats
    float* beta      = alpha + (long long)Bp * Np;     // 3,200,000 floats

    fused_pass_kernel<<<TOTAL_BLOCKS, THREADS>>>(
        x, x_scaler, dim_weight, w, out_small, alpha, beta);
}

// round 10
// speedup vs baseline: 1.0247x; 1.0247x over previous
#include <cuda_runtime.h>

#define Bp 400
#define Np 8000
#define Dp 100
#define SCALERp 4

#define TILE 4                 // rows per warp-tile (ping-pong register buffer)
#define WARPS 4
#define THREADS 128
#define TILES_PER_WARP 100     // 400 rows per warp
#define ROWS_PER_BLOCK (WARPS * TILE * TILES_PER_WARP)   // 1600
#define BLOCKS_PER_B (Np / ROWS_PER_BLOCK)               // 5
#define TOTAL_BLOCKS (Bp * BLOCKS_PER_B)                 // 2000
#define RSTRIDE 28             // floats per buf row; 112B = 16B-aligned, conflict-free
#define BUFROWS 8              // rows 0-3: pa, rows 4-7: pb

// Deterministic per-(b,chunk) pooled partials: [B][BLOCKS_PER_B][D]
__device__ float g_partial[Bp * BLOCKS_PER_B * Dp];
__device__ int   g_cnt = 0;    // last-block election; self-resetting each launch

__device__ __forceinline__ float tanh_approx(float x) {
    float y;
    asm("tanh.approx.f32 %0, %1;" : "=f"(y) : "f"(x));
    return y;
}

__global__ __launch_bounds__(THREADS, 8)   // force <=64 regs -> 8 blocks/SM
void fused_pass_kernel(const float* __restrict__ x,
                       const float* __restrict__ x_scaler,
                       const float* __restrict__ dim_weight,
                       const float* __restrict__ w,
                       float* __restrict__ out_small,
                       float* __restrict__ alpha_out,
                       float* __restrict__ beta_out)
{
    const int b    = blockIdx.x / BLOCKS_PER_B;
    const int c    = blockIdx.x % BLOCKS_PER_B;
    const int warp = threadIdx.x >> 5;
    const int lane = threadIdx.x & 31;

    __shared__ __align__(16) float s_red[WARPS][BUFROWS * RSTRIDE]; // 3.6 KB
    __shared__ float s_acc[WARPS][Dp];                              // 1.6 KB
    __shared__ bool  s_last;

    // Lane l (<25) owns dims [4l, 4l+4)
    float4 dw4 = make_float4(0.f, 0.f, 0.f, 0.f);
    float4 w14 = make_float4(0.f, 0.f, 0.f, 0.f);
    if (lane < 25) {
        dw4 = *reinterpret_cast<const float4*>(dim_weight + 4 * lane);
        w14.x = w[(4 * lane + 0) * 2 + 1];
        w14.y = w[(4 * lane + 1) * 2 + 1];
        w14.z = w[(4 * lane + 2) * 2 + 1];
        w14.w = w[(4 * lane + 3) * 2 + 1];
    }

    float4 acc = make_float4(0.f, 0.f, 0.f, 0.f);
    float* buf = s_red[warp];
    const long long rowbase = (long long)b * Np;

    // Reducing lanes: 0-3 sum pa rows 0-3; 16-19 sum pb rows 4-7.
    const bool redlane = (lane < 4) | ((lane >= 16) & (lane < 20));
    const int  redrow  = (lane < 4) ? lane : (lane - 12);   // buf row index

    // Ping-pong register tiles (4 rows each = 32 regs total)
    float4 v[2][TILE];

    // Preload tile 0
    {
        const float4* base4 = reinterpret_cast<const float4*>(
            x + (rowbase + c * ROWS_PER_BLOCK + warp * TILE) * Dp);
        if (lane < 25) {
            #pragma unroll
            for (int r = 0; r < TILE; r++) v[0][r] = base4[r * 25 + lane];
        } else {
            #pragma unroll
            for (int r = 0; r < TILE; r++) v[0][r] = make_float4(0.f,0.f,0.f,0.f);
        }
    }

    #pragma unroll 2
    for (int t = 0; t < TILES_PER_WARP; t++) {
        const int cur = t & 1;
        const int n0  = c * ROWS_PER_BLOCK + (t * WARPS + warp) * TILE;

        // ---- 1. Prefetch next tile (branch predicated off for last iter)
        if ((t + 1 < TILES_PER_WARP) & (lane < 25)) {
            const float4* nb = reinterpret_cast<const float4*>(
                x + (rowbase + n0 + WARPS * TILE) * Dp);
            #pragma unroll
            for (int r = 0; r < TILE; r++) v[cur ^ 1][r] = nb[r * 25 + lane];
        }

        // ---- 2. Partial dots, row-major into the transpose buffer
        if (lane < 25) {
            #pragma unroll
            for (int r = 0; r < TILE; r++) {
                const float4 q = v[cur][r];
                buf[r * RSTRIDE + lane] =
                    (q.x * dw4.x + q.y * dw4.y) + (q.z * dw4.z + q.w * dw4.w);
                buf[(r + TILE) * RSTRIDE + lane] =
                    (q.x * w14.x + q.y * w14.y) + (q.z * w14.z + q.w * w14.w);
            }
        }
        __syncwarp();

        // ---- 3. Reduce: 6 LDS.128 + 1 LDS.32, one running float4 (low regs)
        float sum = 0.f;
        if (redlane) {
            const float4* row = reinterpret_cast<const float4*>(buf + redrow * RSTRIDE);
            float4 s4 = row[0];
            #pragma unroll
            for (int l = 1; l < 6; l++) {
                const float4 q = row[l];
                s4.x += q.x; s4.y += q.y; s4.z += q.z; s4.w += q.w;
            }
            sum = ((s4.x + s4.y) + (s4.z + s4.w)) + buf[redrow * RSTRIDE + 24];
        }
        const float a = tanh_approx(sum);   // valid in lanes 0..3 (rows 0..3)
        if (lane < 4)
            alpha_out[rowbase + n0 + lane] = a;
        else if (redlane)
            beta_out[rowbase + n0 + (lane - 16)] = sum;

        // ---- 4. Pooled accumulation from registers.
        // First shfl_sync is the convergence point: all reducing lanes have
        // consumed their LDS values, so buf may be overwritten next tile.
        #pragma unroll
        for (int r = 0; r < TILE; r++) {
            const float ar = __shfl_sync(0xffffffffu, a, r);
            const float4 q = v[cur][r];
            acc.x += ar * q.x;
            acc.y += ar * q.y;
            acc.z += ar * q.z;
            acc.w += ar * q.w;
        }
    }

    // ---- Block-reduce the 4 warp accumulators (deterministic)
    if (lane < 25) {
        s_acc[warp][lane * 4 + 0] = acc.x;
        s_acc[warp][lane * 4 + 1] = acc.y;
        s_acc[warp][lane * 4 + 2] = acc.z;
        s_acc[warp][lane * 4 + 3] = acc.w;
    }
    __syncthreads();
    for (int d = threadIdx.x; d < Dp; d += THREADS) {
        float sum = 0.f;
        #pragma unroll
        for (int wp = 0; wp < WARPS; wp++) sum += s_acc[wp][d];
        g_partial[((long long)b * BLOCKS_PER_B + c) * Dp + d] = sum;
    }

    // ---- Last-arriving block performs the final [B,2] head (deterministic)
    __threadfence();
    if (threadIdx.x == 0) {
        int old = atomicAdd(&g_cnt, 1);
        s_last = (old == TOTAL_BLOCKS - 1);
    }
    __syncthreads();
    if (!s_last) return;
    if (threadIdx.x == 0) g_cnt = 0;      // reset for next graph replay

    for (int b2 = warp; b2 < Bp; b2 += WARPS) {
        float4 f4 = make_float4(0.f, 0.f, 0.f, 0.f);
        if (lane < 25) {
            #pragma unroll
            for (int cc = 0; cc < BLOCKS_PER_B; cc++) {
                const float4 g = *reinterpret_cast<const float4*>(
                    g_partial + ((long long)b2 * BLOCKS_PER_B + cc) * Dp + 4 * lane);
                f4.x += g.x; f4.y += g.y; f4.z += g.z; f4.w += g.w;
            }
        }
        float p0 = 0.f, p1 = 0.f;
        if (lane < 25) {
            p0 = f4.x * w[(4*lane+0)*2+0] + f4.y * w[(4*lane+1)*2+0]
               + f4.z * w[(4*lane+2)*2+0] + f4.w * w[(4*lane+3)*2+0];
            p1 = f4.x * w[(4*lane+0)*2+1] + f4.y * w[(4*lane+1)*2+1]
               + f4.z * w[(4*lane+2)*2+1] + f4.w * w[(4*lane+3)*2+1];
        }
        #pragma unroll
        for (int off = 16; off; off >>= 1) {
            p0 += __shfl_xor_sync(0xffffffffu, p0, off);
            p1 += __shfl_xor_sync(0xffffffffu, p1, off);
        }
        if (lane == 0) {
            #pragma unroll
            for (int s = 0; s < SCALERp; s++) {
                const float xs = x_scaler[b2 * SCALERp + s];
                p0 += xs * w[(Dp + s) * 2 + 0];
                p1 += xs * w[(Dp + s) * 2 + 1];
            }
            out_small[b2 * 2 + 0] = p0;
            out_small[b2 * 2 + 1] = p1;
        }
    }
}

extern "C" void kernel_launch(void* const* d_in, const int* in_sizes, int n_in,
                              void* d_out, int out_size)
{
    // metadata order == setup_inputs order: x, x_scaler, dim_weight, w
    const float* x          = (const float*)d_in[0];
    const float* x_scaler   = (const float*)d_in[1];
    const float* dim_weight = (const float*)d_in[2];
    const float* w          = (const float*)d_in[3];

    // Output flattening in reference-return order: out [B,2], alpha [B,1,N], beta [B,N]
    float* out_base  = (float*)d_out;
    float* out_small = out_base;                       // 800 floats
    float* alpha     = out_base + Bp * 2;              // 3,200,000 floats
    float* beta      = alpha + (long long)Bp * Np;     // 3,200,000 floats

    fused_pass_kernel<<<TOTAL_BLOCKS, THREADS>>>(
        x, x_scaler, dim_weight, w, out_small, alpha, beta);
}